// round 17
// baseline (speedup 1.0000x reference)
#include <cuda_runtime.h>

// NaturalCubicSplinePotential — GB300 sm_103a
//
// R16: two-segment contiguous addressing. A block's balanced range (~4724
// float4) is smaller than one slab (16384 float4), so it crosses at most ONE
// slab boundary -> split into <=2 contiguous segments, each with a constant
// base pointer. Inner loop is pbase[i*NT]: one IMAD, zero slab-decode ALU
// (kills R13's per-iter >>14/&16383/64-bit add; measured alu 15.5%).
//
// Verified-kept (R15 WIN base, 25.09us): balanced partition, grid 888 = 148x6
// exact single wave = 8 marginals x 111 equal ranges; conflict-free
// float4/NSLOT=8 slotted gather (L1 floor ~16us measured); folded gather
// address (addr = bits(tm)*128 + prebiased base, wrap-exact); TABN=224
// (PADL=48, covers |x|<=7); closed-form [1,4,1] inverse (31-tap conv); magic
// floor + midpoint recentering; unroll 4 (bracketed optimal); fused
// deterministic last-block reduction.

#define NM 8
#define NN 128
#define TABN 224
#define PADL 48
#define NSLOT 8
#define EVAL_BLOCKS 888
#define BLOCKS_PER_M 111
#define F4_PER_M 524288            // float4 per marginal (32 slabs x 16384)
#define NTHREADS 256
#define CONV_R 15

__device__ float g_part[EVAL_BLOCKS];
__device__ unsigned int g_ticket;   // zero-init; self-resets each call

#define LOG2_LAM 1.89996863f        // log2(2+sqrt(3))
#define INV_D0   1.07735027f        // 1/(1-lam^-2)
#define MAGIC    12582912.0f        // 1.5 * 2^23
// (0x4B400000 * 128) mod 2^32 = 0xA0000000 ; bias = -that
#define ADDR_BIAS 0x60000000u

// ---------------------------------------------------------------------------
__device__ __forceinline__ void eval_lane(float xv, unsigned tbase, float& acc)
{
    // t = (x+4)*15.875 + 48 (pad), midpoint-shifted: t5 = x*15.875 + 111.0
    const float t5 = __fmaf_rn(xv, 15.875f, 111.0f);
    const float tm = t5 + MAGIC;                    // round(t5) == floor(t) a.e.
    const unsigned addr = __float_as_uint(tm) * 128u + tbase;  // one IMAD
    const float v = t5 - (tm - MAGIC);              // v = u - 0.5 in [-0.5,0.5)
    float cx, cy, cz, cw;
    asm("ld.shared.v4.f32 {%0,%1,%2,%3}, [%4];"
        : "=f"(cx), "=f"(cy), "=f"(cz), "=f"(cw) : "r"(addr));
    acc += __fmaf_rn(v, __fmaf_rn(v, __fmaf_rn(v, cw, cz), cy), cx);
}

__global__ void __launch_bounds__(NTHREADS, 6)
eval_kernel(const float4* __restrict__ x4,
            const float* __restrict__ nodal,
            float* __restrict__ out)
{
    __shared__ float4 tab[TABN * NSLOT];                // 28 KB, lane-slotted
    __shared__ float  ysh[NN];
    __shared__ float  pw[256];                          // pw[k] = lam^{-k}
    __shared__ float  srsh[NN + 2 * (CONV_R + 1)];      // padded (-1)^j * r_j
    __shared__ float  csh[NN];
    __shared__ float  wsum[NTHREADS / 32];
    __shared__ bool   amLast;

    const int tid = threadIdx.x;
    const int b   = blockIdx.x;
    const int m   = b / BLOCKS_PER_M;                   // marginal 0..7
    const int q   = b - m * BLOCKS_PER_M;               // 0..110

    // balanced float4 range of this marginal (marginal-linear indices)
    const int jstart = (int)(((unsigned long long)q       * F4_PER_M) / BLOCKS_PER_M);
    const int jend   = (int)(((unsigned long long)(q + 1) * F4_PER_M) / BLOCKS_PER_M);

    // ---- prologue: closed-form spline solve --------------------------------
    if (tid < NN)
        ysh[tid] = nodal[m * NN + tid];
    pw[tid] = exp2f(-LOG2_LAM * (float)tid);
    if (tid < NN + 2 * (CONV_R + 1))
        srsh[tid] = 0.0f;
    __syncthreads();

    const float inv_h2 = (127.0f / 8.0f) * (127.0f / 8.0f);
    if (tid >= 1 && tid <= 126) {
        float r = 3.0f * (ysh[tid - 1] - 2.0f * ysh[tid] + ysh[tid + 1]) * inv_h2;
        srsh[(CONV_R + 1) + tid] = (tid & 1) ? -r : r;
    }
    __syncthreads();

    if (tid < NN) {
        const int i = tid;
        float c = 0.0f;
        if (i >= 1 && i <= 126) {
#pragma unroll
            for (int dj = -CONV_R; dj <= CONV_R; ++dj) {
                const int j  = i + dj;
                const int jc = min(max(j, 1), 126);
                const int mi = min(i, jc);
                const int mx = max(i, jc);
                const float w = pw[(dj < 0 ? -dj : dj) + 1]
                              * (1.0f - pw[2 * mi])
                              * (1.0f - pw[2 * (127 - mx)]);
                c = __fmaf_rn(w, srsh[(CONV_R + 1) + j], c);
            }
            c *= INV_D0;
            if (i & 1) c = -c;
        }
        csh[i] = c;
    }
    __syncthreads();

    // ---- padded + midpoint-recentered table, 8 slots -----------------------
    if (tid < TABN) {
        const float h  = 8.0f / 127.0f;
        const float h2 = h * h;
        const int j  = tid;
        const int it = j - PADL;
        const int k  = min(max(it, 0), 126);
        const float s = (float)(it - k) + 0.5f;     // shift incl. midpoint

        const float A  = ysh[k];
        const float c0 = csh[k];
        const float c1 = csh[k + 1];
        const float B  = (ysh[k + 1] - A) - h2 * (2.0f * c0 + c1) * (1.0f / 3.0f);
        const float C  = c0 * h2;
        const float D  = (c1 - c0) * h2 * (1.0f / 3.0f);

        const float4 cf = make_float4(A + s * (B + s * (C + s * D)),
                                      B + s * (2.0f * C + 3.0f * D * s),
                                      C + 3.0f * D * s,
                                      D);
#pragma unroll
        for (int sl = 0; sl < NSLOT; ++sl)
            tab[j * NSLOT + sl] = cf;
    }
    __syncthreads();

    // ---- main evaluation: <=2 contiguous segments --------------------------
    unsigned tabu32;
    asm("{ .reg .u64 t; cvta.to.shared.u64 t, %1; cvt.u32.u64 %0, t; }"
        : "=r"(tabu32) : "l"(tab));
    const unsigned tbase = tabu32 + (unsigned)((tid & 7) * 16) + ADDR_BIAS;

    float a0 = 0.0f, a1 = 0.0f, a2 = 0.0f, a3 = 0.0f;

    // segment boundary: first slab edge at/after jstart
    const int cut = min(jend, (jstart & ~16383) + 16384);

#pragma unroll 1
    for (int seg = 0; seg < 2; ++seg) {
        const int js = seg ? cut : jstart;
        const int je = seg ? jend : cut;
        if (js >= je) continue;
        // marginal-linear j -> global float4: slab = js>>14 (constant in seg)
        const float4* pbase = x4 + (((size_t)(js >> 14)) << 17) + (m << 14)
                                 + (js & 16383);
        const int count = je - js;
#pragma unroll 4
        for (int i = tid; i < count; i += NTHREADS) {
            const float4 v = pbase[i];
            eval_lane(v.x, tbase, a0);
            eval_lane(v.y, tbase, a1);
            eval_lane(v.z, tbase, a2);
            eval_lane(v.w, tbase, a3);
        }
    }

    float s = (a0 + a1) + (a2 + a3);
#pragma unroll
    for (int o = 16; o > 0; o >>= 1)
        s += __shfl_xor_sync(0xFFFFFFFFu, s, o);

    if ((tid & 31) == 0)
        wsum[tid >> 5] = s;
    __syncthreads();

    if (tid == 0) {
        float t = 0.0f;
#pragma unroll
        for (int w = 0; w < NTHREADS / 32; ++w)
            t += wsum[w];
        g_part[b] = t;
        __threadfence();
        const unsigned int ticket = atomicAdd(&g_ticket, 1u);
        amLast = (ticket == EVAL_BLOCKS - 1);
    }
    __syncthreads();

    // ---- last block: deterministic fixed-order final reduction -------------
    if (amLast) {
        __threadfence();
        float r = 0.0f;
#pragma unroll
        for (int i = 0; i < 4; ++i) {
            const int idx = tid + i * NTHREADS;
            if (idx < EVAL_BLOCKS)
                r += g_part[idx];
        }

        __shared__ float sh[NTHREADS];
        sh[tid] = r;
        __syncthreads();
#pragma unroll
        for (int st = NTHREADS / 2; st > 0; st >>= 1) {
            if (tid < st)
                sh[tid] += sh[tid + st];
            __syncthreads();
        }
        if (tid == 0) {
            out[0] = sh[0];
            g_ticket = 0u;   // reset for next call / graph replay
        }
    }
}

// ---------------------------------------------------------------------------
extern "C" void kernel_launch(void* const* d_in, const int* in_sizes, int n_in,
                              void* d_out, int out_size)
{
    const float* x     = (const float*)d_in[0];        // (32,8,256,256) fp32
    const float* nodal = (const float*)d_in[1];        // (8,128) fp32
    float* out = (float*)d_out;

    eval_kernel<<<EVAL_BLOCKS, NTHREADS>>>((const float4*)x, nodal, out);
}